// round 3
// baseline (speedup 1.0000x reference)
#include <cuda_runtime.h>
#include <math.h>

#define NMAX 50000
#define EMAX 800000
#define GMAX 1000
#define LEAK 0.01f
#define EPS  1e-5f
#define CDIV(a,b) (((a)+(b)-1)/(b))

// ---------------- scratch ----------------------------------------------------
__device__ float g_bufA[NMAX*128];
__device__ float g_bufB[NMAX*128];
__device__ float g_bufC[NMAX*128];
__device__ int   g_indeg[NMAX];
__device__ int   g_off[NMAX+1];
__device__ int   g_cur[NMAX];
__device__ int   g_csr[EMAX];
__device__ float g_dinv[NMAX];     // rsqrt(indeg+1)
__device__ float g_rcnt[NMAX];     // 1/max(indeg,1)
__device__ float g_colsum[256];    // L1:0..127  L2:128..191  L3:192..223
__device__ float g_colsq[256];
__device__ float g_scale[256];
__device__ float g_shift[256];
__device__ float g_pool[GMAX*32];

// ---------------- degree / CSR ----------------------------------------------
__global__ void deg_kernel(const int* __restrict__ dst, int nE) {
    int e = blockIdx.x * blockDim.x + threadIdx.x;
    if (e < nE) atomicAdd(&g_indeg[dst[e]], 1);
}

// single-block scan: off/cur + dinv/rcnt
__global__ void scan_kernel(int n) {
    __shared__ int part[1024];
    int tid = threadIdx.x;
    int chunk = CDIV(n, 1024);
    int start = tid * chunk;
    int end   = min(start + chunk, n);
    int s = 0;
    for (int i = start; i < end; i++) s += g_indeg[i];
    part[tid] = s;
    __syncthreads();
    for (int off = 1; off < 1024; off <<= 1) {
        int v = (tid >= off) ? part[tid - off] : 0;
        __syncthreads();
        part[tid] += v;
        __syncthreads();
    }
    int run = (tid > 0) ? part[tid - 1] : 0;
    for (int i = start; i < end; i++) {
        int d = g_indeg[i];
        g_off[i] = run;
        g_cur[i] = run;
        g_dinv[i] = rsqrtf((float)(d + 1));
        g_rcnt[i] = 1.0f / (float)(d > 0 ? d : 1);
        run += d;
    }
    if (end == n && start < n) g_off[n] = run;
}

__global__ void fill_csr_kernel(const int* __restrict__ src,
                                const int* __restrict__ dst, int nE) {
    int e = blockIdx.x * blockDim.x + threadIdx.x;
    if (e < nE) {
        int p = atomicAdd(&g_cur[dst[e]], 1);
        g_csr[p] = src[e];
    }
}

// ---------------- GEMM: Y[n,M] = X'[n,K] @ W[K,M] ---------------------------
// APPLY: X' = lrelu(bn(X)) with scale/shift at OFF.  PRESCALE: *= dinv[row].
template <int K, int M, int ROWS, int PRESCALE, int APPLY, int OFF>
__global__ void gemm_kernel(const float* __restrict__ X, const float* __restrict__ W,
                            float* __restrict__ Y, int n) {
    const int RG  = 128 / M;
    const int BR  = RG * ROWS;
    const int PBR = BR + 4;
    __shared__ float xs[K * PBR];
    int tid = threadIdx.x;
    int r0  = blockIdx.x * BR;
    for (int i = tid; i < BR * K; i += 128) {
        int r = i / K, k = i % K;
        int row = r0 + r;
        float v = (row < n) ? X[row * K + k] : 0.0f;
        if (APPLY) {
            v = fmaf(v, g_scale[OFF + k], g_shift[OFF + k]);
            v = (v >= 0.0f) ? v : LEAK * v;
        }
        xs[k * PBR + r] = v;
    }
    __syncthreads();
    int col = tid % M;
    int rg  = tid / M;
    float acc[ROWS];
#pragma unroll
    for (int r = 0; r < ROWS; r++) acc[r] = 0.0f;
#pragma unroll 4
    for (int k = 0; k < K; k++) {
        float w = W[k * M + col];
        const float4* xv = (const float4*)&xs[k * PBR + rg * ROWS];
#pragma unroll
        for (int r4 = 0; r4 < ROWS / 4; r4++) {
            float4 xx = xv[r4];
            acc[r4*4+0] = fmaf(xx.x, w, acc[r4*4+0]);
            acc[r4*4+1] = fmaf(xx.y, w, acc[r4*4+1]);
            acc[r4*4+2] = fmaf(xx.z, w, acc[r4*4+2]);
            acc[r4*4+3] = fmaf(xx.w, w, acc[r4*4+3]);
        }
    }
#pragma unroll
    for (int r = 0; r < ROWS; r++) {
        int row = r0 + rg * ROWS + r;
        if (row < n) {
            float v = acc[r];
            if (PRESCALE) v *= g_dinv[row];
            Y[row * M + col] = v;
        }
    }
}

// SAGE fused GEMM: Y = AGG @ Wl + lrelu(bn1(H)) @ Wr   (K=128, M=64)
// + column stats of Y into g_colsum/colsq at offset 128.
template <int K, int M, int ROWS>
__global__ void sage_gemm_kernel(const float* __restrict__ H, const float* __restrict__ AGG,
                                 const float* __restrict__ Wl, const float* __restrict__ Wr,
                                 float* __restrict__ Y, int n) {
    const int RG  = 128 / M;          // 2
    const int BR  = RG * ROWS;        // 16
    const int PBR = BR + 4;
    __shared__ float hs[K * PBR];
    __shared__ float as[K * PBR];
    __shared__ float cs[M], cq[M];
    int tid = threadIdx.x;
    int r0  = blockIdx.x * BR;
    if (tid < M) { cs[tid] = 0.0f; cq[tid] = 0.0f; }
    for (int i = tid; i < BR * K; i += 128) {
        int r = i / K, k = i % K;
        int row = r0 + r;
        float hv = 0.0f, av = 0.0f;
        if (row < n) {
            hv = H[row * K + k];
            hv = fmaf(hv, g_scale[k], g_shift[k]);
            hv = (hv >= 0.0f) ? hv : LEAK * hv;
            av = AGG[row * K + k];
        }
        hs[k * PBR + r] = hv;
        as[k * PBR + r] = av;
    }
    __syncthreads();
    int col = tid % M;
    int rg  = tid / M;
    float acc[ROWS];
#pragma unroll
    for (int r = 0; r < ROWS; r++) acc[r] = 0.0f;
#pragma unroll 2
    for (int k = 0; k < K; k++) {
        float wl = Wl[k * M + col];
        float wr = Wr[k * M + col];
        const float4* hv = (const float4*)&hs[k * PBR + rg * ROWS];
        const float4* av = (const float4*)&as[k * PBR + rg * ROWS];
#pragma unroll
        for (int r4 = 0; r4 < ROWS / 4; r4++) {
            float4 hh = hv[r4];
            float4 aa = av[r4];
            acc[r4*4+0] = fmaf(aa.x, wl, fmaf(hh.x, wr, acc[r4*4+0]));
            acc[r4*4+1] = fmaf(aa.y, wl, fmaf(hh.y, wr, acc[r4*4+1]));
            acc[r4*4+2] = fmaf(aa.z, wl, fmaf(hh.z, wr, acc[r4*4+2]));
            acc[r4*4+3] = fmaf(aa.w, wl, fmaf(hh.w, wr, acc[r4*4+3]));
        }
    }
    float ps = 0.0f, pq = 0.0f;
#pragma unroll
    for (int r = 0; r < ROWS; r++) {
        int row = r0 + rg * ROWS + r;
        if (row < n) {
            Y[row * M + col] = acc[r];
            ps += acc[r];
            pq += acc[r] * acc[r];
        }
    }
    atomicAdd(&cs[col], ps);
    atomicAdd(&cq[col], pq);
    __syncthreads();
    if (tid < M) {
        atomicAdd(&g_colsum[128 + tid], cs[tid]);
        atomicAdd(&g_colsq[128 + tid],  cq[tid]);
    }
}

// ---------------- CSR gathers ------------------------------------------------
// Layer-1 GCN gather (F=128) + column stats (offset 0). 512 threads / 16 nodes.
__global__ void gather128_gcn_stats(const float* __restrict__ Hin,
                                    float* __restrict__ Hout, int n) {
    __shared__ float cs[128], cq[128];
    int tid = threadIdx.x;
    if (tid < 128) { cs[tid] = 0.0f; cq[tid] = 0.0f; }
    __syncthreads();
    int warp = (blockIdx.x * 512 + tid) >> 5;
    int lane = tid & 31;
    if (warp < n) {
        int beg = g_off[warp], end = g_off[warp + 1];
        const float4* H4 = (const float4*)Hin;
        float4 acc = H4[warp * 32 + lane];                 // self (pre-scaled by dinv)
#pragma unroll 4
        for (int e = beg; e < end; e++) {
            int s = __ldg(&g_csr[e]);
            float4 v = H4[s * 32 + lane];
            acc.x += v.x; acc.y += v.y; acc.z += v.z; acc.w += v.w;
        }
        float sc = g_dinv[warp];
        acc.x *= sc; acc.y *= sc; acc.z *= sc; acc.w *= sc;
        ((float4*)Hout)[warp * 32 + lane] = acc;
        int c = lane * 4;
        atomicAdd(&cs[c+0], acc.x); atomicAdd(&cq[c+0], acc.x*acc.x);
        atomicAdd(&cs[c+1], acc.y); atomicAdd(&cq[c+1], acc.y*acc.y);
        atomicAdd(&cs[c+2], acc.z); atomicAdd(&cq[c+2], acc.z*acc.z);
        atomicAdd(&cs[c+3], acc.w); atomicAdd(&cq[c+3], acc.w*acc.w);
    }
    __syncthreads();
    if (tid < 128) {
        atomicAdd(&g_colsum[tid], cs[tid]);
        atomicAdd(&g_colsq[tid],  cq[tid]);
    }
}

// Layer-2 SAGE mean gather (F=128); applies BN1+lrelu to each loaded row.
__global__ void gather128_sage_apply(const float* __restrict__ Hin,
                                     float* __restrict__ Hout, int n) {
    int warp = (blockIdx.x * blockDim.x + threadIdx.x) >> 5;
    int lane = threadIdx.x & 31;
    if (warp >= n) return;
    float4 sc4 = ((const float4*)g_scale)[lane];
    float4 sh4 = ((const float4*)g_shift)[lane];
    int beg = g_off[warp], end = g_off[warp + 1];
    const float4* H4 = (const float4*)Hin;
    float4 acc = make_float4(0.f, 0.f, 0.f, 0.f);
#pragma unroll 4
    for (int e = beg; e < end; e++) {
        int s = __ldg(&g_csr[e]);
        float4 v = H4[s * 32 + lane];
        float a;
        a = fmaf(v.x, sc4.x, sh4.x); acc.x += (a >= 0.f) ? a : LEAK * a;
        a = fmaf(v.y, sc4.y, sh4.y); acc.y += (a >= 0.f) ? a : LEAK * a;
        a = fmaf(v.z, sc4.z, sh4.z); acc.z += (a >= 0.f) ? a : LEAK * a;
        a = fmaf(v.w, sc4.w, sh4.w); acc.w += (a >= 0.f) ? a : LEAK * a;
    }
    float r = g_rcnt[warp];
    acc.x *= r; acc.y *= r; acc.z *= r; acc.w *= r;
    ((float4*)Hout)[warp * 32 + lane] = acc;
}

// F=32 GCN gather; optional stats at offset 192. 512 threads / 16 nodes.
template <int STATS>
__global__ void gather32_kernel(const float* __restrict__ Hin,
                                float* __restrict__ Hout, int n) {
    __shared__ float cs[32], cq[32];
    int tid = threadIdx.x;
    if (STATS) {
        if (tid < 32) { cs[tid] = 0.0f; cq[tid] = 0.0f; }
        __syncthreads();
    }
    int warp = (blockIdx.x * 512 + tid) >> 5;
    int lane = tid & 31;
    if (warp < n) {
        int beg = g_off[warp], end = g_off[warp + 1];
        float acc = Hin[warp * 32 + lane];
#pragma unroll 4
        for (int e = beg; e < end; e++) {
            int s = __ldg(&g_csr[e]);
            acc += Hin[s * 32 + lane];
        }
        acc *= g_dinv[warp];
        Hout[warp * 32 + lane] = acc;
        if (STATS) {
            atomicAdd(&cs[lane], acc);
            atomicAdd(&cq[lane], acc * acc);
        }
    }
    if (STATS) {
        __syncthreads();
        if (tid < 32) {
            atomicAdd(&g_colsum[192 + tid], cs[tid]);
            atomicAdd(&g_colsq[192 + tid],  cq[tid]);
        }
    }
}

// ---------------- BN finalize ------------------------------------------------
__global__ void bn_finalize_kernel(const float* __restrict__ gamma,
                                   const float* __restrict__ beta, int off, float invn) {
    int c = threadIdx.x;
    float m   = g_colsum[off + c] * invn;
    float var = g_colsq[off + c] * invn - m * m;
    float sc  = gamma[c] * rsqrtf(var + EPS);
    g_scale[off + c] = sc;
    g_shift[off + c] = beta[c] - m * sc;
}

// ---------------- pool + link ------------------------------------------------
__global__ void pool_kernel(const float* __restrict__ H, const int* __restrict__ batch,
                            const float* __restrict__ b4, int n) {
    int t = blockIdx.x * blockDim.x + threadIdx.x;
    int node = t / 8, j = t % 8;
    if (node >= n) return;
    int g = batch[node];
    float4 v = ((const float4*)H)[node * 8 + j];
    float4 bb = ((const float4*)b4)[j];
    v.x += bb.x; v.y += bb.y; v.z += bb.z; v.w += bb.w;
    float4* p = ((float4*)g_pool) + g * 8 + j;
    asm volatile("red.global.add.v4.f32 [%0], {%1,%2,%3,%4};"
                 :: "l"(p), "f"(v.x), "f"(v.y), "f"(v.z), "f"(v.w) : "memory");
}

__global__ void link_kernel(const int* __restrict__ li, float* __restrict__ out, int L) {
    int w = (blockIdx.x * blockDim.x + threadIdx.x) / 32;
    int lane = threadIdx.x & 31;
    if (w >= L) return;
    int a = li[w], b = li[L + w];
    float v = g_pool[a * 32 + lane] * g_pool[b * 32 + lane];
#pragma unroll
    for (int off = 16; off > 0; off >>= 1)
        v += __shfl_xor_sync(0xFFFFFFFFu, v, off);
    if (lane == 0) out[w] = 1.0f / (1.0f + expf(-v));
}

// ---------------- launch -----------------------------------------------------
extern "C" void kernel_launch(void* const* d_in, const int* in_sizes, int n_in,
                              void* d_out, int out_size) {
    int base = 4;
    if (n_in >= 20 && in_sizes[4] == 1) base = 5;

    const float* x    = (const float*)d_in[0];
    const int*   ei   = (const int*)d_in[1];
    const int*   batch= (const int*)d_in[2];
    const int*   li   = (const int*)d_in[3];
    const float* W1   = (const float*)d_in[base + 0];
    const float* g1   = (const float*)d_in[base + 2];
    const float* be1  = (const float*)d_in[base + 3];
    const float* Wl2  = (const float*)d_in[base + 4];
    const float* Wr2  = (const float*)d_in[base + 6];
    const float* g2   = (const float*)d_in[base + 7];
    const float* be2  = (const float*)d_in[base + 8];
    const float* W3   = (const float*)d_in[base + 9];
    const float* g3   = (const float*)d_in[base + 11];
    const float* be3  = (const float*)d_in[base + 12];
    const float* W4   = (const float*)d_in[base + 13];
    const float* b4   = (const float*)d_in[base + 14];
    float* out = (float*)d_out;

    const int N = in_sizes[0] / 128;
    const int E = in_sizes[1] / 2;
    const int L = in_sizes[3] / 2;
    const int* src = ei;
    const int* dst = ei + E;
    const float invN = 1.0f / (float)N;

    float *bufA, *bufB, *bufC, *poolp, *colsum, *colsq;
    int* indeg;
    cudaGetSymbolAddress((void**)&bufA,   g_bufA);
    cudaGetSymbolAddress((void**)&bufB,   g_bufB);
    cudaGetSymbolAddress((void**)&bufC,   g_bufC);
    cudaGetSymbolAddress((void**)&indeg,  g_indeg);
    cudaGetSymbolAddress((void**)&poolp,  g_pool);
    cudaGetSymbolAddress((void**)&colsum, g_colsum);
    cudaGetSymbolAddress((void**)&colsq,  g_colsq);

    // ---- setup: zero counters, build CSR ----
    cudaMemsetAsync(indeg,  0, N * sizeof(int));
    cudaMemsetAsync(colsum, 0, 256 * sizeof(float));
    cudaMemsetAsync(colsq,  0, 256 * sizeof(float));
    cudaMemsetAsync(poolp,  0, (size_t)GMAX * 32 * sizeof(float));
    deg_kernel<<<CDIV(E, 256), 256>>>(dst, E);
    scan_kernel<<<1, 1024>>>(N);
    fill_csr_kernel<<<CDIV(E, 256), 256>>>(src, dst, E);

    // ---- Layer 1: GCN(128->128); BN stats fused into gather ----
    gemm_kernel<128, 128, 8, 1, 0, 0><<<CDIV(N, 8), 128>>>(x, W1, bufA, N);
    gather128_gcn_stats<<<CDIV(N * 32, 512), 512>>>(bufA, bufB, N);      // raw gcn1 in bufB
    bn_finalize_kernel<<<1, 128>>>(g1, be1, 0, invN);

    // ---- Layer 2: SAGE(128->64); BN1 applied on load, stats2 in epilogue ----
    gather128_sage_apply<<<CDIV(N * 32, 256), 256>>>(bufB, bufC, N);     // mean of h1
    sage_gemm_kernel<128, 64, 8><<<CDIV(N, 16), 128>>>(bufB, bufC, Wl2, Wr2, bufA, N);
    bn_finalize_kernel<<<1, 64>>>(g2, be2, 128, invN);

    // ---- Layer 3: GCN(64->32); BN2 applied on GEMM load, stats3 in gather ----
    gemm_kernel<64, 32, 8, 1, 1, 128><<<CDIV(N, 32), 128>>>(bufA, W3, bufB, N);
    gather32_kernel<1><<<CDIV(N * 32, 512), 512>>>(bufB, bufC, N);       // raw gcn3 in bufC
    bn_finalize_kernel<<<1, 32>>>(g3, be3, 192, invN);

    // ---- Layer 4: GCN(32->32); BN3 applied on GEMM load; b4 folded into pool ----
    gemm_kernel<32, 32, 8, 1, 1, 192><<<CDIV(N, 32), 128>>>(bufC, W4, bufA, N);
    gather32_kernel<0><<<CDIV(N * 32, 512), 512>>>(bufA, bufB, N);

    // ---- pool + link ----
    pool_kernel<<<CDIV(N * 8, 256), 256>>>(bufB, batch, b4, N);
    link_kernel<<<CDIV(L * 32, 256), 256>>>(li, out, L);
}